// round 1
// baseline (speedup 1.0000x reference)
#include <cuda_runtime.h>
#include <cstdint>
#include <math.h>

typedef unsigned long long u64;

// ---------------------------------------------------------------------------
// Packed f32x2 helpers (Blackwell sm_103a): 2x fp32 FMA throughput vs 3-reg FFMA
// ---------------------------------------------------------------------------
__device__ __forceinline__ u64 ffma2(u64 a, u64 b, u64 c) {
    u64 d;
    asm("fma.rn.f32x2 %0, %1, %2, %3;" : "=l"(d) : "l"(a), "l"(b), "l"(c));
    return d;
}
__device__ __forceinline__ u64 pack2(float x, float y) {
    u64 r;
    asm("mov.b64 %0, {%1, %2};" : "=l"(r) : "f"(x), "f"(y));
    return r;
}
__device__ __forceinline__ float2 unpack2(u64 v) {
    float2 f;
    asm("mov.b64 {%0, %1}, %2;" : "=f"(f.x), "=f"(f.y) : "l"(v));
    return f;
}
__device__ __forceinline__ uint32_t smem_u32(const void* p) {
    uint32_t a;
    asm("{ .reg .u64 t; cvta.to.shared.u64 t, %1; cvt.u32.u64 %0, t; }"
        : "=r"(a) : "l"(p));
    return a;
}

// Accurate-enough tanh that does NOT degrade under --use_fast_math.
// (tanhf would lower to tanh.approx.f32, abs err ~2^-11, which random-walks
// past 1e-3 over 1024 recurrent steps. __expf uses ex2.approx, rel err ~2^-22.)
__device__ __forceinline__ float tanh_acc(float x) {
    float e = __expf(2.0f * x);
    return 1.0f - 2.0f / (e + 1.0f);
}

// ---------------------------------------------------------------------------
// Phase 1: x_proj[m][h] = sum_d X[m][d] * W_ih[h][d] + b_ih[h]
// M = 65536, K = D = 256, N = H = 256. Classic smem-tiled GEMM, 128x128 tile,
// 8x8 microtile per thread, f32x2 packed accumulators.
// ---------------------------------------------------------------------------
__global__ void __launch_bounds__(256) xproj_kernel(
    const float* __restrict__ X, const float* __restrict__ Wih,
    const float* __restrict__ bih, float* __restrict__ C)
{
    __shared__ __align__(16) float As[16][128];
    __shared__ __align__(16) float Bs[16][128];

    const int tid = threadIdx.x;
    const int tx  = tid & 15;     // n direction
    const int ty  = tid >> 4;     // m direction
    const int m0  = blockIdx.y * 128;
    const int n0  = blockIdx.x * 128;

    u64 acc[8][4];
#pragma unroll
    for (int m = 0; m < 8; m++)
#pragma unroll
        for (int n = 0; n < 4; n++) acc[m][n] = 0ull;

    for (int k0 = 0; k0 < 256; k0 += 16) {
#pragma unroll
        for (int i = 0; i < 2; i++) {
            int idx = tid + i * 256;         // 0..511
            int row = idx >> 2;              // 0..127
            int kq  = (idx & 3) << 2;        // 0,4,8,12
            float4 xa = *(const float4*)(X + (size_t)(m0 + row) * 256 + k0 + kq);
            As[kq + 0][row] = xa.x; As[kq + 1][row] = xa.y;
            As[kq + 2][row] = xa.z; As[kq + 3][row] = xa.w;
            float4 wa = *(const float4*)(Wih + (size_t)(n0 + row) * 256 + k0 + kq);
            Bs[kq + 0][row] = wa.x; Bs[kq + 1][row] = wa.y;
            Bs[kq + 2][row] = wa.z; Bs[kq + 3][row] = wa.w;
        }
        __syncthreads();

#pragma unroll
        for (int kk = 0; kk < 16; kk++) {
            float4 a0 = *(const float4*)&As[kk][ty * 8];
            float4 a1 = *(const float4*)&As[kk][ty * 8 + 4];
            float4 b0 = *(const float4*)&Bs[kk][tx * 8];
            float4 b1 = *(const float4*)&Bs[kk][tx * 8 + 4];
            u64 bb[4] = { pack2(b0.x, b0.y), pack2(b0.z, b0.w),
                          pack2(b1.x, b1.y), pack2(b1.z, b1.w) };
            float am[8] = { a0.x, a0.y, a0.z, a0.w, a1.x, a1.y, a1.z, a1.w };
#pragma unroll
            for (int m = 0; m < 8; m++) {
                u64 ad = pack2(am[m], am[m]);
#pragma unroll
                for (int n = 0; n < 4; n++) acc[m][n] = ffma2(ad, bb[n], acc[m][n]);
            }
        }
        __syncthreads();
    }

    const int nc = n0 + tx * 8;
    float4 bv0 = *(const float4*)(bih + nc);
    float4 bv1 = *(const float4*)(bih + nc + 4);
#pragma unroll
    for (int m = 0; m < 8; m++) {
        float2 r0 = unpack2(acc[m][0]), r1 = unpack2(acc[m][1]);
        float2 r2 = unpack2(acc[m][2]), r3 = unpack2(acc[m][3]);
        float* cp = C + (size_t)(m0 + ty * 8 + m) * 256 + nc;
        *(float4*)cp       = make_float4(r0.x + bv0.x, r0.y + bv0.y,
                                         r1.x + bv0.z, r1.y + bv0.w);
        *(float4*)(cp + 4) = make_float4(r2.x + bv1.x, r2.y + bv1.y,
                                         r3.x + bv1.z, r3.y + bv1.w);
    }
}

// ---------------------------------------------------------------------------
// Phase 2: recurrent scan. One 2-CTA cluster per batch row (64 clusters,
// 128 CTAs, 256 threads each). W_hh lives entirely in registers:
//   thread (jl, kh) holds W_hh[rank*128 + jl][kh*128 .. kh*128+127]  (64 u64)
// h (256 floats) is broadcast from smem, double-buffered by step parity.
// Each step, each CTA computes its 128 outputs; the halves are exchanged
// via DSMEM stores + per-thread mbarrier.arrive.release.cluster (count=128).
// The remote-k warps (kh != rank) wait on the mbarrier; the local-k warps
// (the writers) never block on it, so DSMEM latency hides under local FMA.
// ---------------------------------------------------------------------------
__device__ __forceinline__ void mbar_wait_cluster(uint32_t addr, uint32_t parity) {
    asm volatile(
        "{\n\t"
        ".reg .pred P;\n\t"
        "LAB_W_%=:\n\t"
        "mbarrier.try_wait.parity.acquire.cluster.shared::cta.b64 P, [%0], %1, 0x989680;\n\t"
        "@P bra.uni LAB_D_%=;\n\t"
        "bra.uni LAB_W_%=;\n\t"
        "LAB_D_%=:\n\t"
        "}"
        :: "r"(addr), "r"(parity) : "memory");
}

__global__ void __cluster_dims__(2, 1, 1) __launch_bounds__(256, 1)
rnn_scan_kernel(const float* __restrict__ Whh, const float* __restrict__ bhh,
                float* __restrict__ out)
{
    __shared__ __align__(16) float h_sm[2][256];   // double-buffered hidden state
    __shared__ float partial_sm[128];
    __shared__ __align__(8) u64 mbar;

    const int tid = threadIdx.x;
    uint32_t rank;
    asm("mov.u32 %0, %%cluster_ctarank;" : "=r"(rank));
    const int      batch = blockIdx.x >> 1;
    const int      jl    = tid & 127;
    const uint32_t kh    = (uint32_t)(tid >> 7);      // which k-half this thread covers
    const int      j     = (int)rank * 128 + jl;      // output index owned (all threads)
    const int      kbase = (int)kh * 128;
    const bool     is_writer = (kh == rank);          // local-k threads: combine + tanh + publish

    // --- load W_hh[j][kbase .. kbase+127] into 64 packed f32x2 registers ---
    u64 w2[64];
    {
        const ulonglong2* wrow = (const ulonglong2*)(Whh + (size_t)j * 256 + kbase);
#pragma unroll
        for (int i = 0; i < 32; i++) {
            ulonglong2 v = wrow[i];
            w2[2 * i] = v.x; w2[2 * i + 1] = v.y;
        }
    }

    // --- init state ---
    h_sm[0][tid] = 0.0f;
    h_sm[1][tid] = 0.0f;
    uint32_t mbar_a = smem_u32(&mbar);
    if (tid == 0)
        asm volatile("mbarrier.init.shared.b64 [%0], 128;" :: "r"(mbar_a) : "memory");
    asm volatile("barrier.cluster.arrive.aligned;" ::: "memory");
    asm volatile("barrier.cluster.wait.aligned;" ::: "memory");

    uint32_t hbase_a = smem_u32(&h_sm[0][0]);
    uint32_t peer = rank ^ 1u;
    uint32_t hbase_peer, mbar_peer;
    asm("mapa.shared::cluster.u32 %0, %1, %2;" : "=r"(hbase_peer) : "r"(hbase_a), "r"(peer));
    asm("mapa.shared::cluster.u32 %0, %1, %2;" : "=r"(mbar_peer)  : "r"(mbar_a),  "r"(peer));

    float* outb = out + (size_t)batch * (1024 * 256) + j;   // column j, stride 256/step
    const float bh = bhh[j];
    float xp_next = is_writer ? outb[0] : 0.0f;             // xp for t=0 (in-place buffer)

    for (int t = 0; t < 1024; t++) {
        // remote-k threads: wait until peer delivered h_{t-1} for our remote half
        if (!is_writer && t > 0)
            mbar_wait_cluster(mbar_a, (uint32_t)((t - 1) & 1));

        const float xp_cur = xp_next;
        if (is_writer && t < 1023)
            xp_next = __ldg(outb + (size_t)(t + 1) * 256);  // prefetch next xp

        // partial dot product over this thread's k-half (broadcast LDS.128)
        const ulonglong2* h4 = (const ulonglong2*)&h_sm[t & 1][kbase];
        u64 acc0 = 0ull, acc1 = 0ull;
#pragma unroll
        for (int i = 0; i < 32; i += 2) {
            ulonglong2 va = h4[i];
            acc0 = ffma2(w2[2 * i],     va.x, acc0);
            acc1 = ffma2(w2[2 * i + 1], va.y, acc1);
            ulonglong2 vb = h4[i + 1];
            acc0 = ffma2(w2[2 * i + 2], vb.x, acc0);
            acc1 = ffma2(w2[2 * i + 3], vb.y, acc1);
        }
        float2 a0 = unpack2(acc0), a1 = unpack2(acc1);
        float s = (a0.x + a0.y) + (a1.x + a1.y);

        if (!is_writer) partial_sm[jl] = s;
        __syncthreads();

        if (is_writer) {
            float tot = s + partial_sm[jl] + xp_cur + bh;
            float h = tanh_acc(tot);
            const int wb = (t + 1) & 1;
            h_sm[wb][j] = h;                                  // local copy
            uint32_t raddr = hbase_peer + (uint32_t)(wb * 256 + j) * 4u;
            asm volatile("st.shared::cluster.f32 [%0], %1;"
                         :: "r"(raddr), "f"(h) : "memory");   // peer copy (DSMEM)
            asm volatile("mbarrier.arrive.release.cluster.shared::cluster.b64 _, [%0];"
                         :: "r"(mbar_peer) : "memory");       // publish (128 arrives/step)
            outb[(size_t)t * 256] = h;                        // final output
        }
        __syncthreads();
    }

    // keep smem alive until peer's in-flight DSMEM stores complete
    asm volatile("barrier.cluster.arrive.aligned;" ::: "memory");
    asm volatile("barrier.cluster.wait.aligned;" ::: "memory");
}

// ---------------------------------------------------------------------------
// Harness entry. Inputs: x, W_ih, W_hh, b_ih, b_hh. Output fp32 [B,T,H].
// x_proj is materialized into d_out, then overwritten in place by h_t.
// Phase 1 fully regenerates x_proj every call -> deterministic under graph replay.
// ---------------------------------------------------------------------------
extern "C" void kernel_launch(void* const* d_in, const int* in_sizes, int n_in,
                              void* d_out, int out_size)
{
    const float* x   = (const float*)d_in[0];
    const float* Wih = (const float*)d_in[1];
    const float* Whh = (const float*)d_in[2];
    const float* bih = (const float*)d_in[3];
    const float* bhh = (const float*)d_in[4];
    float* out = (float*)d_out;

    // Phase 1: x_proj GEMM (M=65536 rows, 128x128 tiles)
    dim3 g1(2, 512);
    xproj_kernel<<<g1, 256>>>(x, Wih, bih, out);

    // Phase 2: recurrent scan, 64 clusters of 2 CTAs
    rnn_scan_kernel<<<128, 256>>>(Whh, bhh, out);
}